// round 2
// baseline (speedup 1.0000x reference)
#include <cuda_runtime.h>
#include <cstdint>

#define TT 2048
#define BB 64
#define II 256
#define HH 512
#define KK 768            // H + I, hx = [h, x]
#define NCTA 128
#define NTHR 128

// Scratch (device globals: allocation APIs are forbidden)
__device__ float g_xT[TT][II][BB];    // x transposed: [t][i][b]
__device__ float g_hT[2][HH][BB];     // hidden state, double buffered, [k][b]
__device__ unsigned g_bar;

static const int SMEM_FLOATS = KK * 32 + 2 * 128 * 64 + 16 * 64 + 4 * 64 + 16;
static const int SMEM_BYTES = SMEM_FLOATS * 4;   // 169,024 B

// ---------------- helpers ----------------
__device__ __forceinline__ void fma2(unsigned long long& d, unsigned long long a,
                                     unsigned long long b) {
    asm volatile("fma.rn.f32x2 %0, %1, %2, %0;" : "+l"(d) : "l"(a), "l"(b));
}

__device__ __forceinline__ void cp16(float* dst_sm, const float* src) {
    unsigned d = (unsigned)__cvta_generic_to_shared(dst_sm);
    asm volatile("cp.async.cg.shared.global [%0], [%1], 16;" :: "r"(d), "l"(src));
}
__device__ __forceinline__ void cp_commit() {
    asm volatile("cp.async.commit_group;");
}
template <int N>
__device__ __forceinline__ void cp_wait() {
    asm volatile("cp.async.wait_group %0;" :: "n"(N));
}

__device__ __forceinline__ float sigmoidf_(float z) {
    return 1.0f / (1.0f + expf(-z));
}

// ---------------- init ----------------
__global__ void init_kernel() {
    int i = blockIdx.x * blockDim.x + threadIdx.x;
    if (i < HH * BB) (&g_hT[0][0][0])[i] = 0.0f;
    if (i == 0) g_bar = 0u;
}

// ---------------- x transpose: x[t][b][i] -> g_xT[t][i][b] ----------------
__global__ void xT_kernel(const float* __restrict__ x) {
    __shared__ float tile[64][65];
    int t = blockIdx.x;
    for (int ic = 0; ic < 4; ++ic) {
        __syncthreads();
        for (int idx = threadIdx.x; idx < 4096; idx += blockDim.x) {
            int b = idx >> 6, i2 = idx & 63;
            tile[b][i2] = x[((size_t)t * BB + b) * II + ic * 64 + i2];
        }
        __syncthreads();
        for (int idx = threadIdx.x; idx < 4096; idx += blockDim.x) {
            int i2 = idx >> 6, b = idx & 63;
            g_xT[t][ic * 64 + i2][b] = tile[b][i2];
        }
    }
}

// ---------------- persistent LSTM ----------------
__global__ void __launch_bounds__(NTHR, 1) lstm_persist(
    const float* __restrict__ Wf, const float* __restrict__ bf,
    const float* __restrict__ Wi, const float* __restrict__ bi,
    const float* __restrict__ Wc, const float* __restrict__ bc,
    const float* __restrict__ Wo, const float* __restrict__ bo,
    float* __restrict__ out)
{
    extern __shared__ float sm[];
    float* Wsd  = sm;                     // [KK][32]  rows duplicated-packed for f32x2
    float* hxs  = Wsd + KK * 32;          // [2][128][64] staged hx chunks
    float* pres = hxs + 2 * 128 * 64;     // [16][64] gate pre-activations
    float* cs   = pres + 16 * 64;         // [4][64] cell state (this CTA's 4 hid units)
    float* bs   = cs + 4 * 64;            // [16] biases

    const int tid  = threadIdx.x;
    const int cta  = blockIdx.x;
    const int hid0 = cta * 4;             // 4 hidden units per CTA
    const int rg   = tid >> 4;            // 0..7 : rows {2rg, 2rg+1}
    const int bg   = tid & 15;            // 0..15: batches 4bg..4bg+3

    // Load weights for this CTA's 16 gate rows: row r = g*4 + j  (g: f,i,c,o)
    for (int idx = tid; idx < KK * 16; idx += NTHR) {
        int k = idx >> 4, r = idx & 15;
        int g = r >> 2, j = r & 3;
        const float* W = (g == 0) ? Wf : (g == 1) ? Wi : (g == 2) ? Wc : Wo;
        float w = W[(size_t)(hid0 + j) * KK + k];
        Wsd[k * 32 + 2 * r]     = w;
        Wsd[k * 32 + 2 * r + 1] = w;
    }
    if (tid < 16) {
        int g = tid >> 2, j = tid & 3;
        const float* Bv = (g == 0) ? bf : (g == 1) ? bi : (g == 2) ? bc : bo;
        bs[tid] = Bv[hid0 + j];
    }
    for (int idx = tid; idx < 4 * 64; idx += NTHR) cs[idx] = 0.0f;
    __syncthreads();

    unsigned bar_target = 0;

    for (int t = 0; t < TT; ++t) {
        const float* hsrc = &g_hT[t & 1][0][0];
        const float* xsrc = &g_xT[t][0][0];

        // stage chunk 0 (k = 0..127, from h)
        {
            float* buf = hxs;
            #pragma unroll
            for (int q = 0; q < 16; ++q) {
                int e = q * NTHR + tid;           // 0..2047 granules of 16B
                cp16(buf + e * 4, hsrc + e * 4);
            }
            cp_commit();
        }

        unsigned long long a00 = 0, a01 = 0, a10 = 0, a11 = 0;

        for (int c = 0; c < 6; ++c) {
            if (c < 5) {
                float* buf = hxs + ((c + 1) & 1) * (128 * 64);
                const float* src = (c < 3) ? (hsrc + (c + 1) * 8192)
                                           : (xsrc + (c - 3) * 8192);
                #pragma unroll
                for (int q = 0; q < 16; ++q) {
                    int e = q * NTHR + tid;
                    cp16(buf + e * 4, src + e * 4);
                }
                cp_commit();
                cp_wait<1>();
            } else {
                cp_wait<0>();
            }
            __syncthreads();

            const float* hb = hxs + (c & 1) * (128 * 64);
            const float* wb = Wsd + c * 128 * 32;
            #pragma unroll 8
            for (int kl = 0; kl < 128; ++kl) {
                ulonglong2 w = *(const ulonglong2*)(wb + kl * 32 + 4 * rg);
                ulonglong2 v = *(const ulonglong2*)(hb + kl * 64 + 4 * bg);
                fma2(a00, w.x, v.x);  fma2(a01, w.x, v.y);
                fma2(a10, w.y, v.x);  fma2(a11, w.y, v.y);
            }
            __syncthreads();
        }

        // dump pre-activations to smem
        {
            ulonglong2 p0; p0.x = a00; p0.y = a01;
            ulonglong2 p1; p1.x = a10; p1.y = a11;
            *(ulonglong2*)(pres + (2 * rg)     * 64 + 4 * bg) = p0;
            *(ulonglong2*)(pres + (2 * rg + 1) * 64 + 4 * bg) = p1;
        }
        __syncthreads();

        // gates + state update; each (j, b) cell owned by exactly one thread
        float* hdst = &g_hT[(t + 1) & 1][0][0];
        #pragma unroll
        for (int cell = tid; cell < 256; cell += NTHR) {
            int b = cell >> 2, j = cell & 3;
            float zf = pres[(0 + j)  * 64 + b] + bs[j];
            float zi = pres[(4 + j)  * 64 + b] + bs[4 + j];
            float zc = pres[(8 + j)  * 64 + b] + bs[8 + j];
            float zo = pres[(12 + j) * 64 + b] + bs[12 + j];
            float fg = sigmoidf_(zf);
            float ig = sigmoidf_(zi);
            float og = sigmoidf_(zo);
            float cn = fg * cs[j * 64 + b] + ig * tanhf(zc);
            float hn = og * tanhf(cn);
            cs[j * 64 + b] = cn;
            hdst[(hid0 + j) * BB + b] = hn;
            out[((size_t)t * BB + b) * HH + hid0 + j] = hn;
            if (t == TT - 1) {
                out[(size_t)TT * BB * HH + (size_t)b * HH + hid0 + j] = hn;               // h_last
                out[(size_t)TT * BB * HH + (size_t)BB * HH + (size_t)b * HH + hid0 + j] = cn; // c_last
            }
        }

        // grid-wide barrier (monotonic counter; double-buffered state makes 1 sync/step safe)
        bar_target += NCTA;
        __threadfence();
        __syncthreads();
        if (tid == 0) {
            atomicAdd(&g_bar, 1u);
            unsigned v;
            for (;;) {
                asm volatile("ld.acquire.gpu.global.u32 %0, [%1];"
                             : "=r"(v) : "l"(&g_bar));
                if (v >= bar_target) break;
                __nanosleep(64);
            }
        }
        __syncthreads();
    }
}

// ---------------- launch ----------------
extern "C" void kernel_launch(void* const* d_in, const int* in_sizes, int n_in,
                              void* d_out, int out_size) {
    const float* x  = (const float*)d_in[0];
    const float* Wf = (const float*)d_in[1];
    const float* bf = (const float*)d_in[2];
    const float* Wi = (const float*)d_in[3];
    const float* bi = (const float*)d_in[4];
    const float* Wc = (const float*)d_in[5];
    const float* bc = (const float*)d_in[6];
    const float* Wo = (const float*)d_in[7];
    const float* bo = (const float*)d_in[8];
    float* out = (float*)d_out;

    cudaFuncSetAttribute(lstm_persist,
                         cudaFuncAttributeMaxDynamicSharedMemorySize, SMEM_BYTES);

    init_kernel<<<(HH * BB + 255) / 256, 256>>>();
    xT_kernel<<<TT, 256>>>(x);
    lstm_persist<<<NCTA, NTHR, SMEM_BYTES>>>(Wf, bf, Wi, bi, Wc, bc, Wo, bo, out);
}

// round 3
// speedup vs baseline: 1.2488x; 1.2488x over previous
#include <cuda_runtime.h>
#include <cstdint>

#define TT 2048
#define BB 64
#define II 256
#define HH 512
#define KK 768            // H + I, hx = [h, x]
#define NCTA 128
#define NTHR 256

// Scratch (device globals: allocation APIs are forbidden)
__device__ float g_xT[TT][II][BB];      // x transposed: [t][i][b]
__device__ float g_hT[2][HH][BB];       // hidden state, double buffered, [k][b]
__device__ unsigned g_flags[NCTA][32];  // per-CTA arrival flag, 128B stride

// smem: Wsd[KK][32] dup-packed + 2 x hx chunk [128][64] + pres[4][16][64] + cs[4][64] + bs[16]
static const int SMEM_FLOATS = KK * 32 + 2 * 128 * 64 + 4 * 16 * 64 + 4 * 64 + 16;
static const int SMEM_BYTES = SMEM_FLOATS * 4;   // 181,312 B

// ---------------- helpers ----------------
__device__ __forceinline__ void fma2(unsigned long long& d, unsigned long long a,
                                     unsigned long long b) {
    asm volatile("fma.rn.f32x2 %0, %1, %2, %0;" : "+l"(d) : "l"(a), "l"(b));
}

__device__ __forceinline__ void cp16(float* dst_sm, const float* src) {
    unsigned d = (unsigned)__cvta_generic_to_shared(dst_sm);
    asm volatile("cp.async.cg.shared.global [%0], [%1], 16;" :: "r"(d), "l"(src));
}
__device__ __forceinline__ void cp_commit() {
    asm volatile("cp.async.commit_group;");
}
template <int N>
__device__ __forceinline__ void cp_wait() {
    asm volatile("cp.async.wait_group %0;" :: "n"(N));
}

__device__ __forceinline__ float fast_sigmoid(float z) {
    return __fdividef(1.0f, 1.0f + __expf(-z));
}
__device__ __forceinline__ float fast_tanh(float z) {
    return __fdividef(2.0f, 1.0f + __expf(-2.0f * z)) - 1.0f;
}

// ---------------- init (runs every launch: resets state + flags) ----------------
__global__ void init_kernel() {
    int i = blockIdx.x * blockDim.x + threadIdx.x;
    if (i < HH * BB) (&g_hT[0][0][0])[i] = 0.0f;
    if (i < NCTA * 32) (&g_flags[0][0])[i] = 0u;
}

// ---------------- x transpose: x[t][b][i] -> g_xT[t][i][b] ----------------
__global__ void xT_kernel(const float* __restrict__ x) {
    __shared__ float tile[64][65];
    int t = blockIdx.x;
    for (int ic = 0; ic < 4; ++ic) {
        __syncthreads();
        for (int idx = threadIdx.x; idx < 4096; idx += blockDim.x) {
            int b = idx >> 6, i2 = idx & 63;
            tile[b][i2] = x[((size_t)t * BB + b) * II + ic * 64 + i2];
        }
        __syncthreads();
        for (int idx = threadIdx.x; idx < 4096; idx += blockDim.x) {
            int i2 = idx >> 6, b = idx & 63;
            g_xT[t][ic * 64 + i2][b] = tile[b][i2];
        }
    }
}

// ---------------- persistent LSTM ----------------
__global__ void __launch_bounds__(NTHR, 1) lstm_persist(
    const float* __restrict__ Wf, const float* __restrict__ bf,
    const float* __restrict__ Wi, const float* __restrict__ bi,
    const float* __restrict__ Wc, const float* __restrict__ bc,
    const float* __restrict__ Wo, const float* __restrict__ bo,
    float* __restrict__ out)
{
    extern __shared__ float sm[];
    float* Wsd  = sm;                     // [KK][32]  rows duplicated-packed for f32x2
    float* hxs  = Wsd + KK * 32;          // [2][128][64] staged hx chunks
    float* pres = hxs + 2 * 128 * 64;     // [4][16][64] partial pre-activations (per k-quarter)
    float* cs   = pres + 4 * 16 * 64;     // [4][64] cell state (this CTA's 4 hid units)
    float* bs   = cs + 4 * 64;            // [16] biases

    const int tid  = threadIdx.x;
    const int cta  = blockIdx.x;
    const int hid0 = cta * 4;             // 4 hidden units per CTA
    const int q    = tid >> 6;            // k-quarter 0..3 (32 kl of each chunk)
    const int lq   = tid & 63;
    const int rg   = lq >> 4;             // 0..3 : rows 4rg .. 4rg+3
    const int bg   = lq & 15;             // 0..15: batches 4bg .. 4bg+3

    // Load weights for this CTA's 16 gate rows: row r = g*4 + j  (g: f,i,c,o)
    // Duplicated-packed: Wsd[k*32 + 2r] = Wsd[k*32 + 2r + 1] = W[r][k]
    for (int idx = tid; idx < KK * 16; idx += NTHR) {
        int k = idx >> 4, r = idx & 15;
        int g = r >> 2, j = r & 3;
        const float* W = (g == 0) ? Wf : (g == 1) ? Wi : (g == 2) ? Wc : Wo;
        float w = W[(size_t)(hid0 + j) * KK + k];
        Wsd[k * 32 + 2 * r]     = w;
        Wsd[k * 32 + 2 * r + 1] = w;
    }
    if (tid < 16) {
        int g = tid >> 2, j = tid & 3;
        const float* Bv = (g == 0) ? bf : (g == 1) ? bi : (g == 2) ? bc : bo;
        bs[tid] = Bv[tid >= 0 ? (hid0 + j) : 0];
    }
    for (int idx = tid; idx < 4 * 64; idx += NTHR) cs[idx] = 0.0f;
    __syncthreads();

    for (int t = 0; t < TT; ++t) {
        const float* hsrc = &g_hT[t & 1][0][0];
        const float* xsrc = &g_xT[t][0][0];

        // stage chunk 0 (k = 0..127, from h)
        {
            #pragma unroll
            for (int it = 0; it < 8; ++it) {
                int e = it * NTHR + tid;           // 0..2047 granules of 16B
                cp16(hxs + e * 4, hsrc + e * 4);
            }
            cp_commit();
        }

        unsigned long long a0 = 0, a1 = 0, a2 = 0, a3 = 0,
                           a4 = 0, a5 = 0, a6 = 0, a7 = 0;

        for (int c = 0; c < 6; ++c) {
            if (c < 5) {
                float* buf = hxs + ((c + 1) & 1) * (128 * 64);
                const float* src = (c < 3) ? (hsrc + (c + 1) * 8192)
                                           : (xsrc + (c - 3) * 8192);
                #pragma unroll
                for (int it = 0; it < 8; ++it) {
                    int e = it * NTHR + tid;
                    cp16(buf + e * 4, src + e * 4);
                }
                cp_commit();
                cp_wait<1>();
            } else {
                cp_wait<0>();
            }
            __syncthreads();

            // this k-group computes kl = q*32 .. q*32+31 within the chunk
            const float* hb = hxs + (c & 1) * (128 * 64) + q * 32 * 64 + 4 * bg;
            const float* wb = Wsd + (c * 128 + q * 32) * 32 + 8 * rg;
            #pragma unroll 4
            for (int i = 0; i < 32; ++i) {
                ulonglong2 wA = *(const ulonglong2*)(wb + i * 32);        // rows 4rg, 4rg+1 (dup)
                ulonglong2 wB = *(const ulonglong2*)(wb + i * 32 + 4);    // rows 4rg+2, 4rg+3 (dup)
                ulonglong2 v  = *(const ulonglong2*)(hb + i * 64);        // batches 4bg..4bg+3
                fma2(a0, wA.x, v.x);  fma2(a1, wA.x, v.y);
                fma2(a2, wA.y, v.x);  fma2(a3, wA.y, v.y);
                fma2(a4, wB.x, v.x);  fma2(a5, wB.x, v.y);
                fma2(a6, wB.y, v.x);  fma2(a7, wB.y, v.y);
            }
            __syncthreads();
        }

        // dump partial pre-activations: pres[q][row][b]
        {
            ulonglong2 p;
            p.x = a0; p.y = a1;
            *(ulonglong2*)(pres + (q * 16 + 4 * rg + 0) * 64 + 4 * bg) = p;
            p.x = a2; p.y = a3;
            *(ulonglong2*)(pres + (q * 16 + 4 * rg + 1) * 64 + 4 * bg) = p;
            p.x = a4; p.y = a5;
            *(ulonglong2*)(pres + (q * 16 + 4 * rg + 2) * 64 + 4 * bg) = p;
            p.x = a6; p.y = a7;
            *(ulonglong2*)(pres + (q * 16 + 4 * rg + 3) * 64 + 4 * bg) = p;
        }
        __syncthreads();

        // gates + state update: 256 cells, one per thread
        float* hdst = &g_hT[(t + 1) & 1][0][0];
        {
            int b = tid >> 2, j = tid & 3;
            float zf = bs[j],      zi = bs[4 + j],
                  zc = bs[8 + j],  zo = bs[12 + j];
            #pragma unroll
            for (int qq = 0; qq < 4; ++qq) {
                zf += pres[(qq * 16 + 0  + j) * 64 + b];
                zi += pres[(qq * 16 + 4  + j) * 64 + b];
                zc += pres[(qq * 16 + 8  + j) * 64 + b];
                zo += pres[(qq * 16 + 12 + j) * 64 + b];
            }
            float fg = fast_sigmoid(zf);
            float ig = fast_sigmoid(zi);
            float og = fast_sigmoid(zo);
            float cn = fg * cs[j * 64 + b] + ig * fast_tanh(zc);
            float hn = og * fast_tanh(cn);
            cs[j * 64 + b] = cn;
            hdst[(hid0 + j) * BB + b] = hn;
            out[((size_t)t * BB + b) * HH + hid0 + j] = hn;
            if (t == TT - 1) {
                out[(size_t)TT * BB * HH + (size_t)b * HH + hid0 + j] = hn;                    // h_last
                out[(size_t)TT * BB * HH + (size_t)BB * HH + (size_t)b * HH + hid0 + j] = cn;  // c_last
            }
        }

        // ---- grid barrier: per-CTA flags (distinct 128B lines), no atomics ----
        __threadfence();
        __syncthreads();
        if (tid == 0) {
            asm volatile("st.release.gpu.global.u32 [%0], %1;"
                         :: "l"(&g_flags[cta][0]), "r"((unsigned)(t + 1)));
        }
        if (tid < NCTA) {
            const unsigned* fp = &g_flags[tid][0];
            unsigned v;
            do {
                asm volatile("ld.acquire.gpu.global.u32 %0, [%1];" : "=r"(v) : "l"(fp));
            } while (v < (unsigned)(t + 1));
        }
        __syncthreads();
    }
}

// ---------------- launch ----------------
extern "C" void kernel_launch(void* const* d_in, const int* in_sizes, int n_in,
                              void* d_out, int out_size) {
    const float* x  = (const float*)d_in[0];
    const float* Wf = (const float*)d_in[1];
    const float* bf = (const float*)d_in[2];
    const float* Wi = (const float*)d_in[3];
    const float* bi = (const float*)d_in[4];
    const float* Wc = (const float*)d_in[5];
    const float* bc = (const float*)d_in[6];
    const float* Wo = (const float*)d_in[7];
    const float* bo = (const float*)d_in[8];
    float* out = (float*)d_out;

    cudaFuncSetAttribute(lstm_persist,
                         cudaFuncAttributeMaxDynamicSharedMemorySize, SMEM_BYTES);

    init_kernel<<<(HH * BB + 255) / 256, 256>>>();
    xT_kernel<<<TT, 256>>>(x);
    lstm_persist<<<NCTA, NTHR, SMEM_BYTES>>>(Wf, bf, Wi, bi, Wc, bc, Wo, bo, out);
}